// round 15
// baseline (speedup 1.0000x reference)
#include <cuda_runtime.h>
#include <math.h>

#define NCTA 128
#define NTHR 512
#define WG_F4 12336                  // 48 gatecols x 257 (padded: conflict-free 4-distinct reads)
#define OV_F4 2112                   // overlay: ph3 weights 8x257=2056 / reductions / ph1
#define SMEM_F4 (WG_F4 + OV_F4)
#define SMEM_BYTES (SMEM_F4 * 16)    // 231168 <= 232448

typedef unsigned long long u64;
typedef ulonglong2 ull2;

__device__ __forceinline__ u64 fma2(u64 a, u64 b, u64 c) {
    u64 d;
    asm("fma.rn.f32x2 %0, %1, %2, %3;" : "=l"(d) : "l"(a), "l"(b), "l"(c));
    return d;
}
__device__ __forceinline__ float hsum(u64 v) {
    union { u64 u; float f[2]; } x; x.u = v;
    return x.f[0] + x.f[1];
}
__device__ __forceinline__ float sigm(float x) { return 1.f / (1.f + expf(-x)); }
__device__ __forceinline__ float softplusf(float x) {
    return fmaxf(x, 0.f) + log1pf(expf(-fabsf(x)));
}

// ---------------- persistent state ----------------
__device__ float g_emb[64 * 1024];
__device__ float g_det[2][64 * 1024];
__device__ float g_h1[64 * 512];
__device__ float g_hq[64 * 512];
__device__ float g_stoch[64 * 32];
__device__ float g_obsq[64 * 256 * 512];     // obs @ Wq1[:,1024:]^T + bq1
__device__ float g_actemb[64 * 256 * 1024];  // act @ Wsa[:,32:]^T + bsa
__device__ unsigned g_leaf[8][32];
__device__ unsigned g_root;
__device__ volatile unsigned g_gen;

__device__ __forceinline__ void gbar() {
    __syncthreads();
    if (threadIdx.x == 0) {
        __threadfence();
        unsigned gen = g_gen;
        int l = blockIdx.x & 7;
        if (atomicAdd(&g_leaf[l][0], 1u) == 15) {
            g_leaf[l][0] = 0;
            __threadfence();
            if (atomicAdd(&g_root, 1u) == 7) {
                g_root = 0;
                __threadfence();
                g_gen = gen + 1;
            }
        }
        while (g_gen == gen) { }
        __threadfence();   // CCTL.IVALL: invalidate this SM's L1 (coherence point)
    }
    __syncthreads();
}

// ======== pre-pass A: g_obsq ========
__global__ void __launch_bounds__(256)
obsq_kernel(const float* __restrict__ obs, const float* __restrict__ Wq1,
            const float* __restrict__ bq1) {
    extern __shared__ float4 S[];
    const int tid = threadIdx.x, lane = tid & 31, wrp = tid >> 5;
    const int rt = blockIdx.x >> 2, ct = blockIdx.x & 3;
    const int r0 = rt * 64, c0 = ct * 128;
    const int rh = wrp >> 2, cgq = wrp & 3;

    u64 acc[32];
    #pragma unroll
    for (int j = 0; j < 32; ++j) acc[j] = 0ull;

    for (int c = 0; c < 16; ++c) {
        for (int i = tid; i < 1024; i += 256) {
            int row = i >> 4, k4 = i & 15;
            S[row * 17 + k4] = *(const float4*)(obs + (size_t)(r0 + row) * 1024 + c * 64 + k4 * 4);
        }
        for (int i = tid; i < 2048; i += 256) {
            int col = i >> 4, k4 = i & 15;
            S[1088 + col * 16 + k4] =
                *(const float4*)(Wq1 + (size_t)(c0 + col) * 2048 + 1024 + c * 64 + k4 * 4);
        }
        __syncthreads();
        const ull2* xr = (const ull2*)(S + (rh * 32 + lane) * 17);
        const ull2* wb = (const ull2*)(S + 1088 + (cgq * 32) * 16);
        for (int k4 = 0; k4 < 16; ++k4) {
            ull2 x = xr[k4];
            #pragma unroll
            for (int j = 0; j < 32; ++j) {
                ull2 w = wb[j * 16 + k4];
                acc[j] = fma2(w.x, x.x, acc[j]);
                acc[j] = fma2(w.y, x.y, acc[j]);
            }
        }
        __syncthreads();
    }
    int r = r0 + rh * 32 + lane;
    #pragma unroll
    for (int j = 0; j < 32; ++j) {
        int col = c0 + cgq * 32 + j;
        g_obsq[(size_t)r * 512 + col] = hsum(acc[j]) + bq1[col];
    }
}

// ======== pre-pass B: g_actemb ========
__global__ void __launch_bounds__(256)
actemb_kernel(const float* __restrict__ act, const float* __restrict__ Wsa,
              const float* __restrict__ bsa) {
    extern __shared__ float4 S[];
    const int tid = threadIdx.x, lane = tid & 31, wrp = tid >> 5;
    const int rt = blockIdx.x >> 3, ct = blockIdx.x & 7;
    const int r0 = rt * 64, c0 = ct * 128;
    const int rh = wrp >> 2, cgq = wrp & 3;

    for (int i = tid; i < 1024; i += 256) {
        int row = i >> 4, k4 = i & 15;
        S[row * 17 + k4] = *(const float4*)(act + (size_t)(r0 + row) * 64 + k4 * 4);
    }
    for (int i = tid; i < 2048; i += 256) {
        int col = i >> 4, k4 = i & 15;
        S[1088 + col * 16 + k4] =
            *(const float4*)(Wsa + (size_t)(c0 + col) * 96 + 32 + k4 * 4);
    }
    __syncthreads();

    u64 acc[32];
    #pragma unroll
    for (int j = 0; j < 32; ++j) acc[j] = 0ull;
    const ull2* xr = (const ull2*)(S + (rh * 32 + lane) * 17);
    const ull2* wb = (const ull2*)(S + 1088 + (cgq * 32) * 16);
    for (int k4 = 0; k4 < 16; ++k4) {
        ull2 x = xr[k4];
        #pragma unroll
        for (int j = 0; j < 32; ++j) {
            ull2 w = wb[j * 16 + k4];
            acc[j] = fma2(w.x, x.x, acc[j]);
            acc[j] = fma2(w.y, x.y, acc[j]);
        }
    }
    int r = r0 + rh * 32 + lane;
    #pragma unroll
    for (int j = 0; j < 32; ++j) {
        int col = c0 + cgq * 32 + j;
        g_actemb[(size_t)r * 1024 + col] = hsum(acc[j]) + bsa[col];
    }
}

// ======== persistent rollout ========
__global__ void __launch_bounds__(NTHR, 1)
rssm_kernel(const float* __restrict__ obs,   const float* __restrict__ act,
            const float* __restrict__ nzp,   const float* __restrict__ nzq,
            const float* __restrict__ Wsa, const float* __restrict__ bsa,
            const float* __restrict__ Wih, const float* __restrict__ bih,
            const float* __restrict__ Whh, const float* __restrict__ bhh,
            const float* __restrict__ Wp1, const float* __restrict__ bp1,
            const float* __restrict__ Wp2, const float* __restrict__ bp2,
            const float* __restrict__ Wq1, const float* __restrict__ bq1,
            const float* __restrict__ Wq2, const float* __restrict__ bq2,
            float* __restrict__ out)
{
    extern __shared__ float4 S[];
    float4* wG = S;                   // 48 gatecols x 257 (resident)
    float4* xb = S + WG_F4;           // overlay

    const int tid  = threadIdx.x;
    const int lane = tid & 31;
    const int wrp  = tid >> 5;
    const int c0g  = blockIdx.x * 8;
    const int r0   = lane & 7;
    const int cq   = lane >> 3;       // 0..3

    // GRU ids: 16 warps = h(4 contiguous K-quarters) x gp(2 oc-groups) x mat(2)
    const int h    = wrp & 3;
    const int gp   = (wrp >> 2) & 1;
    const int mat  = wrp >> 3;        // 0: i-gates (x=emb), 1: h-gates (x=det)
    const int oc   = gp * 4 + cq;
    // ph1 ids
    const int pr   = (wrp & 7) * 8 + r0;
    const int pc   = (wrp >> 3) * 4 + cq;
    // ph3 ids
    const int h3   = wrp & 7;         // contiguous K-eighth
    const int rw3  = wrp >> 3;        // row half

    // ---- init ----
    for (int i = blockIdx.x * NTHR + tid; i < 64 * 1024; i += NCTA * NTHR)
        g_det[0][i] = 0.f;
    for (int i = blockIdx.x * NTHR + tid; i < 64 * 32; i += NCTA * NTHR)
        g_stoch[i] = 0.f;
    for (int i = tid; i < WG_F4; i += NTHR) {
        int gc = i / 257, k = i - gc * 257;
        if (k < 256) {
            int col = gc / 6, g = gc - col * 6;
            const float* srow = (g < 3)
                ? (Wih + ((size_t)(c0g + col) + 1024 * g) * 1024)
                : (Whh + ((size_t)(c0g + col) + 1024 * (g - 3)) * 1024);
            wG[i] = *(const float4*)(srow + k * 4);
        }
    }
    gbar();

    const float4* wgm0 = wG + (oc * 6 + mat * 3 + 0) * 257;
    const float4* wgm1 = wG + (oc * 6 + mat * 3 + 1) * 257;
    const float4* wgm2 = wG + (oc * 6 + mat * 3 + 2) * 257;

    for (int t = 0; t < 256; ++t) {
        const int p = t & 1;
        const float* detP = g_det[p];
        float*       detN = g_det[p ^ 1];

        // ===== phase 1: emb = relu(stoch @ Ws^T + actemb), K=32 =====
        {
            float4* stS = xb;           // 64 x 9
            float4* wS1 = xb + 576;     // 8 x 9
            {
                int row = tid >> 3, k4 = tid & 7;
                stS[row * 9 + k4] = *(const float4*)(g_stoch + row * 32 + k4 * 4);
            }
            if (tid < 64) {
                int c = tid >> 3, k4 = tid & 7;
                wS1[c * 9 + k4] = *(const float4*)(Wsa + (size_t)(c0g + c) * 96 + k4 * 4);
            }
            __syncthreads();
            u64 a = 0;
            #pragma unroll
            for (int k4 = 0; k4 < 8; ++k4) {
                ull2 x = *(const ull2*)(stS + pr * 9 + k4);
                ull2 w = *(const ull2*)(wS1 + pc * 9 + k4);
                a = fma2(w.x, x.x, a); a = fma2(w.y, x.y, a);
            }
            int col = c0g + pc;
            float base = g_actemb[((size_t)pr * 256 + t) * 1024 + col];
            g_emb[(size_t)pr * 1024 + col] = fmaxf(hsum(a) + base, 0.f);
        }
        gbar();

        // ===== phase 2: GRU — flat barrier-free loop, x direct from L2 =====
        {
            const float* xg = mat ? detP : g_emb;

            u64 acc[24];
            #pragma unroll
            for (int n = 0; n < 24; ++n) acc[n] = 0ull;

            const int kbase = h * 64;
            #pragma unroll 4
            for (int q4 = 0; q4 < 64; ++q4) {
                int k4 = kbase + q4;
                float4 wAf = wgm0[k4];
                float4 wBf = wgm1[k4];
                float4 wCf = wgm2[k4];
                ull2 wa = *(ull2*)&wAf;
                ull2 wb = *(ull2*)&wBf;
                ull2 wc = *(ull2*)&wCf;
                #pragma unroll
                for (int i = 0; i < 8; ++i) {
                    float4 xf = *(const float4*)(xg + (size_t)(r0 + 8 * i) * 1024 + k4 * 4);
                    ull2 x = *(ull2*)&xf;
                    acc[i*3+0] = fma2(wa.x, x.x, acc[i*3+0]);
                    acc[i*3+0] = fma2(wa.y, x.y, acc[i*3+0]);
                    acc[i*3+1] = fma2(wb.x, x.x, acc[i*3+1]);
                    acc[i*3+1] = fma2(wb.y, x.y, acc[i*3+1]);
                    acc[i*3+2] = fma2(wc.x, x.x, acc[i*3+2]);
                    acc[i*3+2] = fma2(wc.y, x.y, acc[i*3+2]);
                }
            }

            float f[24];
            #pragma unroll
            for (int n = 0; n < 24; ++n) f[n] = hsum(acc[n]);
            float* R = (float*)xb;

            __syncthreads();
            if (h >= 2) {
                float* pp = R + (((h - 2) * 4 + gp * 2 + mat) * 32 + lane) * 24;
                #pragma unroll
                for (int n = 0; n < 24; ++n) pp[n] = f[n];
            }
            __syncthreads();
            if (h < 2) {
                const float* pp = R + ((h * 4 + gp * 2 + mat) * 32 + lane) * 24;
                #pragma unroll
                for (int n = 0; n < 24; ++n) f[n] += pp[n];
            }
            __syncthreads();
            if (h == 1) {
                float* pp = R + ((gp * 2 + mat) * 32 + lane) * 24;
                #pragma unroll
                for (int n = 0; n < 24; ++n) pp[n] = f[n];
            }
            __syncthreads();
            if (h == 0) {
                const float* pp = R + ((gp * 2 + mat) * 32 + lane) * 24;
                #pragma unroll
                for (int n = 0; n < 24; ++n) f[n] += pp[n];
            }
            __syncthreads();
            if (h == 0 && mat == 1) {
                int col = c0g + oc;
                float* pp = R + (gp * 32 + lane) * 24;
                #pragma unroll
                for (int i = 0; i < 8; ++i)
                    #pragma unroll
                    for (int m = 0; m < 3; ++m)
                        pp[i * 3 + m] = f[i * 3 + m] + bhh[col + 1024 * m];
            }
            __syncthreads();
            if (h == 0 && mat == 0) {
                int col = c0g + oc;
                const float* ph = R + (gp * 32 + lane) * 24;
                #pragma unroll
                for (int i = 0; i < 8; ++i) {
                    int row = r0 + 8 * i;
                    float ir = f[i*3+0] + bih[col];
                    float iz = f[i*3+1] + bih[col + 1024];
                    float in = f[i*3+2] + bih[col + 2048];
                    float hr = ph[i*3+0], hz = ph[i*3+1], hn = ph[i*3+2];
                    float r  = sigm(ir + hr);
                    float z  = sigm(iz + hz);
                    float n  = tanhf(in + r * hn);
                    float hp = detP[(size_t)row * 1024 + col];
                    float hw = (1.f - z) * n + z * hp;
                    detN[(size_t)row * 1024 + col] = hw;
                    out[((size_t)row * 256 + t) * 1216 + col] = hw;
                }
            }
        }
        gbar();

        // ===== phase 3: h1/hq first layers — weights staged once, x from L2 =====
        {
            const bool isQ = blockIdx.x & 1;
            const int  c0  = (blockIdx.x >> 1) * 8;
            const float* W1 = isQ ? Wq1 : Wp1;
            const size_t K1 = isQ ? 2048 : 1024;
            float4* wS = xb;            // 8 cols x 257

            for (int i = tid; i < 2048; i += NTHR) {
                int c = i >> 8, k4 = i & 255;
                wS[c * 257 + k4] = *(const float4*)(W1 + (size_t)(c0 + c) * K1 + k4 * 4);
            }
            __syncthreads();

            u64 acc[8];
            #pragma unroll
            for (int n = 0; n < 8; ++n) acc[n] = 0ull;

            const int kb3 = h3 * 32;
            const float4* w0p = wS + (cq * 2) * 257;
            const float4* w1p = wS + (cq * 2 + 1) * 257;
            #pragma unroll 4
            for (int q4 = 0; q4 < 32; ++q4) {
                int k4 = kb3 + q4;
                float4 w0f = w0p[k4];
                float4 w1f = w1p[k4];
                ull2 w0 = *(ull2*)&w0f;
                ull2 w1 = *(ull2*)&w1f;
                #pragma unroll
                for (int i = 0; i < 4; ++i) {
                    int row = rw3 * 32 + r0 + 8 * i;
                    float4 xf = *(const float4*)(detN + (size_t)row * 1024 + k4 * 4);
                    ull2 x = *(ull2*)&xf;
                    acc[i*2+0] = fma2(w0.x, x.x, acc[i*2+0]);
                    acc[i*2+0] = fma2(w0.y, x.y, acc[i*2+0]);
                    acc[i*2+1] = fma2(w1.x, x.x, acc[i*2+1]);
                    acc[i*2+1] = fma2(w1.y, x.y, acc[i*2+1]);
                }
            }

            float f[8];
            #pragma unroll
            for (int n = 0; n < 8; ++n) f[n] = hsum(acc[n]);
            float* Rf = (float*)xb;
            __syncthreads();            // wS no longer needed; reuse as reduction
            if (h3 > 0) {
                float* pp = Rf + (((h3 - 1) * 2 + rw3) * 32 + lane) * 8;
                #pragma unroll
                for (int n = 0; n < 8; ++n) pp[n] = f[n];
            }
            __syncthreads();
            if (h3 == 0) {
                for (int s = 0; s < 7; ++s) {
                    const float* pp = Rf + ((s * 2 + rw3) * 32 + lane) * 8;
                    #pragma unroll
                    for (int n = 0; n < 8; ++n) f[n] += pp[n];
                }
                float* dst = isQ ? g_hq : g_h1;
                #pragma unroll
                for (int i = 0; i < 4; ++i) {
                    int row = rw3 * 32 + r0 + 8 * i;
                    #pragma unroll
                    for (int c = 0; c < 2; ++c) {
                        int col = c0 + cq * 2 + c;
                        float base = isQ ? g_obsq[((size_t)row * 256 + t) * 512 + col]
                                         : bp1[col];
                        dst[(size_t)row * 512 + col] = fmaxf(f[i*2+c] + base, 0.f);
                    }
                }
            }
        }
        gbar();

        // ===== phase 4: heads =====
        {
            const int gw = blockIdx.x * 16 + wrp;
            #pragma unroll
            for (int i = 0; i < 2; ++i) {
                int pi    = gw * 2 + i;
                int which = pi & 1;
                int s     = (pi >> 1) & 31;
                int bb    = pi >> 6;
                const float* hv = (which ? g_hq : g_h1) + (size_t)bb * 512;
                const float* W2 = which ? Wq2 : Wp2;
                u64 am = 0, asd = 0;
                #pragma unroll
                for (int q = 0; q < 4; ++q) {
                    float4 xf = __ldcg((const float4*)(hv + lane * 16 + q * 4));
                    ull2 x = *(ull2*)&xf;
                    ull2 u = *(const ull2*)(W2 + (size_t)s * 512 + lane * 16 + q * 4);
                    ull2 v = *(const ull2*)(W2 + (size_t)(s + 32) * 512 + lane * 16 + q * 4);
                    am  = fma2(u.x, x.x, am);  am  = fma2(u.y, x.y, am);
                    asd = fma2(v.x, x.x, asd); asd = fma2(v.y, x.y, asd);
                }
                float sm = hsum(am), ss = hsum(asd);
                #pragma unroll
                for (int o = 16; o; o >>= 1) {
                    sm += __shfl_xor_sync(0xffffffffu, sm, o);
                    ss += __shfl_xor_sync(0xffffffffu, ss, o);
                }
                if (lane == 0) {
                    const float* b2 = which ? bq2 : bp2;
                    float mean = sm + b2[s];
                    float stdv = softplusf(ss + b2[s + 32]) + 1e-5f;
                    const float* nz = which ? nzq : nzp;
                    float e  = nz[((size_t)bb * 256 + t) * 32 + s];
                    float st = mean + stdv * e;
                    size_t base = ((size_t)bb * 256 + t) * 1216 + 1024 + which * 96;
                    out[base + s]      = mean;
                    out[base + 32 + s] = stdv;
                    out[base + 64 + s] = st;
                    if (which) g_stoch[bb * 32 + s] = st;
                }
            }
        }
        gbar();
    }
}

extern "C" void kernel_launch(void* const* d_in, const int* in_sizes, int n_in,
                              void* d_out, int out_size) {
    (void)in_sizes; (void)n_in; (void)out_size;
    cudaFuncSetAttribute((const void*)obsq_kernel,
                         cudaFuncAttributeMaxDynamicSharedMemorySize, 50176);
    cudaFuncSetAttribute((const void*)actemb_kernel,
                         cudaFuncAttributeMaxDynamicSharedMemorySize, 50176);
    cudaFuncSetAttribute((const void*)rssm_kernel,
                         cudaFuncAttributeMaxDynamicSharedMemorySize, SMEM_BYTES);
    actemb_kernel<<<2048, 256, 50176>>>(
        (const float*)d_in[1], (const float*)d_in[4], (const float*)d_in[5]);
    obsq_kernel<<<1024, 256, 50176>>>(
        (const float*)d_in[0], (const float*)d_in[14], (const float*)d_in[15]);
    rssm_kernel<<<NCTA, NTHR, SMEM_BYTES>>>(
        (const float*)d_in[0],  (const float*)d_in[1],
        (const float*)d_in[2],  (const float*)d_in[3],
        (const float*)d_in[4],  (const float*)d_in[5],
        (const float*)d_in[6],  (const float*)d_in[7],
        (const float*)d_in[8],  (const float*)d_in[9],
        (const float*)d_in[10], (const float*)d_in[11],
        (const float*)d_in[12], (const float*)d_in[13],
        (const float*)d_in[14], (const float*)d_in[15],
        (const float*)d_in[16], (const float*)d_in[17],
        (float*)d_out);
}

// round 16
// speedup vs baseline: 5.4205x; 5.4205x over previous
#include <cuda_runtime.h>
#include <math.h>

#define NCTA 128
#define NTHR 512
#define SMEM_BYTES (196608 + 24576)   // wfrag(float2 x 24576) + R(float4 x 1536) = 221184

typedef unsigned long long u64;
typedef ulonglong2 ull2;
typedef unsigned int uint32;

__device__ __forceinline__ u64 fma2(u64 a, u64 b, u64 c) {
    u64 d;
    asm("fma.rn.f32x2 %0, %1, %2, %3;" : "=l"(d) : "l"(a), "l"(b), "l"(c));
    return d;
}
__device__ __forceinline__ float hsum(u64 v) {
    union { u64 u; float f[2]; } x; x.u = v;
    return x.f[0] + x.f[1];
}
__device__ __forceinline__ float sigm(float x) { return 1.f / (1.f + expf(-x)); }
__device__ __forceinline__ float softplusf(float x) {
    return fmaxf(x, 0.f) + log1pf(expf(-fabsf(x)));
}
__device__ __forceinline__ float tf32r(float x) {
    float r;
    asm("cvt.rna.tf32.f32 %0, %1;" : "=f"(r) : "f"(x));
    return r;
}
// D(16x8) += A(16x8,tf32) * B(8x8,tf32)
__device__ __forceinline__ void mma8(float* d, float4 av, float2 bv) {
    uint32 a0 = __float_as_uint(av.x), a1 = __float_as_uint(av.y);
    uint32 a2 = __float_as_uint(av.z), a3 = __float_as_uint(av.w);
    uint32 b0 = __float_as_uint(bv.x), b1 = __float_as_uint(bv.y);
    asm volatile(
        "mma.sync.aligned.m16n8k8.row.col.f32.tf32.tf32.f32 "
        "{%0,%1,%2,%3}, {%4,%5,%6,%7}, {%8,%9}, {%0,%1,%2,%3};"
        : "+f"(d[0]), "+f"(d[1]), "+f"(d[2]), "+f"(d[3])
        : "r"(a0), "r"(a1), "r"(a2), "r"(a3), "r"(b0), "r"(b1));
}

// ---------------- persistent state ----------------
__device__ float g_det[2][64 * 1024];        // fp32 deter (recurrence residual + output)
__device__ float g_detf[2][64 * 1024];       // tf32 fragment-packed deter
__device__ float g_embf[64 * 1024];          // tf32 fragment-packed emb
__device__ float g_h1[64 * 512];
__device__ float g_hq[64 * 512];
__device__ float g_stoch[64 * 32];
__device__ float g_obsq[64 * 256 * 512];
__device__ float g_actemb[64 * 256 * 1024];
__device__ float2 g_w1frag[128 * 4096];      // per-CTA ph3 weight fragments
__device__ unsigned g_leaf[8][32];
__device__ unsigned g_root;
__device__ volatile unsigned g_gen;

__device__ __forceinline__ void gbar() {
    __syncthreads();
    if (threadIdx.x == 0) {
        __threadfence();
        unsigned gen = g_gen;
        int l = blockIdx.x & 7;
        if (atomicAdd(&g_leaf[l][0], 1u) == 15) {
            g_leaf[l][0] = 0;
            __threadfence();
            if (atomicAdd(&g_root, 1u) == 7) {
                g_root = 0;
                __threadfence();
                g_gen = gen + 1;
            }
        }
        while (g_gen == gen) { }
        __threadfence();   // CCTL.IVALL — L1 coherence point
    }
    __syncthreads();
}

// fragment word index for element (row 0..63, k 0..1023)
__device__ __forceinline__ int fragIdx(int row, int k) {
    int k8 = k >> 3, rb = row >> 4, rp = row & 15;
    int lane = (rp & 7) * 4 + (k & 3);
    int reg  = ((rp >> 3) & 1) + (((k & 7) >> 2) << 1);
    return ((k8 * 4 + rb) * 32 + lane) * 4 + reg;
}

// ======== pre-pass A: g_obsq = obs @ Wq1[:,1024:]^T + bq1 (fp32) ========
__global__ void __launch_bounds__(256)
obsq_kernel(const float* __restrict__ obs, const float* __restrict__ Wq1,
            const float* __restrict__ bq1) {
    extern __shared__ float4 S[];
    const int tid = threadIdx.x, lane = tid & 31, wrp = tid >> 5;
    const int rt = blockIdx.x >> 2, ct = blockIdx.x & 3;
    const int r0 = rt * 64, c0 = ct * 128;
    const int rh = wrp >> 2, cgq = wrp & 3;

    u64 acc[32];
    #pragma unroll
    for (int j = 0; j < 32; ++j) acc[j] = 0ull;

    for (int c = 0; c < 16; ++c) {
        for (int i = tid; i < 1024; i += 256) {
            int row = i >> 4, k4 = i & 15;
            S[row * 17 + k4] = *(const float4*)(obs + (size_t)(r0 + row) * 1024 + c * 64 + k4 * 4);
        }
        for (int i = tid; i < 2048; i += 256) {
            int col = i >> 4, k4 = i & 15;
            S[1088 + col * 16 + k4] =
                *(const float4*)(Wq1 + (size_t)(c0 + col) * 2048 + 1024 + c * 64 + k4 * 4);
        }
        __syncthreads();
        const ull2* xr = (const ull2*)(S + (rh * 32 + lane) * 17);
        const ull2* wb = (const ull2*)(S + 1088 + (cgq * 32) * 16);
        for (int k4 = 0; k4 < 16; ++k4) {
            ull2 x = xr[k4];
            #pragma unroll
            for (int j = 0; j < 32; ++j) {
                ull2 w = wb[j * 16 + k4];
                acc[j] = fma2(w.x, x.x, acc[j]);
                acc[j] = fma2(w.y, x.y, acc[j]);
            }
        }
        __syncthreads();
    }
    int r = r0 + rh * 32 + lane;
    #pragma unroll
    for (int j = 0; j < 32; ++j) {
        int col = c0 + cgq * 32 + j;
        g_obsq[(size_t)r * 512 + col] = hsum(acc[j]) + bq1[col];
    }
}

// ======== pre-pass B: g_actemb = act @ Wsa[:,32:]^T + bsa (fp32) ========
__global__ void __launch_bounds__(256)
actemb_kernel(const float* __restrict__ act, const float* __restrict__ Wsa,
              const float* __restrict__ bsa) {
    extern __shared__ float4 S[];
    const int tid = threadIdx.x, lane = tid & 31, wrp = tid >> 5;
    const int rt = blockIdx.x >> 3, ct = blockIdx.x & 7;
    const int r0 = rt * 64, c0 = ct * 128;
    const int rh = wrp >> 2, cgq = wrp & 3;

    for (int i = tid; i < 1024; i += 256) {
        int row = i >> 4, k4 = i & 15;
        S[row * 17 + k4] = *(const float4*)(act + (size_t)(r0 + row) * 64 + k4 * 4);
    }
    for (int i = tid; i < 2048; i += 256) {
        int col = i >> 4, k4 = i & 15;
        S[1088 + col * 16 + k4] =
            *(const float4*)(Wsa + (size_t)(c0 + col) * 96 + 32 + k4 * 4);
    }
    __syncthreads();

    u64 acc[32];
    #pragma unroll
    for (int j = 0; j < 32; ++j) acc[j] = 0ull;
    const ull2* xr = (const ull2*)(S + (rh * 32 + lane) * 17);
    const ull2* wb = (const ull2*)(S + 1088 + (cgq * 32) * 16);
    for (int k4 = 0; k4 < 16; ++k4) {
        ull2 x = xr[k4];
        #pragma unroll
        for (int j = 0; j < 32; ++j) {
            ull2 w = wb[j * 16 + k4];
            acc[j] = fma2(w.x, x.x, acc[j]);
            acc[j] = fma2(w.y, x.y, acc[j]);
        }
    }
    int r = r0 + rh * 32 + lane;
    #pragma unroll
    for (int j = 0; j < 32; ++j) {
        int col = c0 + cgq * 32 + j;
        g_actemb[(size_t)r * 1024 + col] = hsum(acc[j]) + bsa[col];
    }
}

// ======== persistent rollout ========
__global__ void __launch_bounds__(NTHR, 1)
rssm_kernel(const float* __restrict__ obs,   const float* __restrict__ act,
            const float* __restrict__ nzp,   const float* __restrict__ nzq,
            const float* __restrict__ Wsa, const float* __restrict__ bsa,
            const float* __restrict__ Wih, const float* __restrict__ bih,
            const float* __restrict__ Whh, const float* __restrict__ bhh,
            const float* __restrict__ Wp1, const float* __restrict__ bp1,
            const float* __restrict__ Wp2, const float* __restrict__ bp2,
            const float* __restrict__ Wq1, const float* __restrict__ bq1,
            const float* __restrict__ Wq2, const float* __restrict__ bq2,
            float* __restrict__ out)
{
    extern __shared__ char SM[];
    float2* wfS = (float2*)SM;                 // 24576 float2: GRU weight frags
    float4* R4  = (float4*)(SM + 196608);      // 1536 float4: reductions / ph1 overlay
    float*  Rf  = (float*)R4;

    const int tid  = threadIdx.x;
    const int lane = tid & 31;
    const int wrp  = tid >> 5;
    const int c0g  = blockIdx.x * 8;
    // GRU warp ids: rb(4) x ks(2) x cth(2)
    const int rb   = wrp & 3;
    const int ks   = (wrp >> 2) & 1;
    const int cth  = wrp >> 3;                 // 0: i-gates (A=emb), 1: h-gates (A=det)
    // ph3 warp ids: rb3(4) x ks3(4)
    const int rb3  = wrp & 3;
    const int ks3  = wrp >> 2;
    // ph1 ids
    const int pr   = (wrp & 7) * 8 + (lane & 7);
    const int pc   = (wrp >> 3) * 4 + (lane >> 3);
    // ph3/per-CTA head assignment
    const bool isQ = blockIdx.x & 1;
    const int  c0  = (blockIdx.x >> 1) * 8;
    const float* W1 = isQ ? Wq1 : Wp1;
    const size_t K1 = isQ ? 2048 : 1024;

    // ---- init: zero state ----
    for (int i = blockIdx.x * NTHR + tid; i < 64 * 1024; i += NCTA * NTHR) {
        g_det[0][i]  = 0.f;
        g_detf[0][i] = 0.f;
    }
    for (int i = blockIdx.x * NTHR + tid; i < 64 * 32; i += NCTA * NTHR)
        g_stoch[i] = 0.f;
    // ---- init: GRU weight fragments into smem (tf32) ----
    for (int i = tid; i < 24576; i += NTHR) {
        int ct = i >> 12, k8 = (i >> 5) & 127, ln = i & 31;
        int g = ct % 3, cm = ct / 3;
        int n = ln >> 2, kl = ln & 3;
        const float* Wm = cm ? Whh : Wih;
        size_t rowo = ((size_t)(g * 1024 + c0g + n)) * 1024 + k8 * 8 + kl;
        wfS[i] = make_float2(tf32r(Wm[rowo]), tf32r(Wm[rowo + 4]));
    }
    // ---- init: ph3 weight fragments into global (tf32) ----
    for (int i = tid; i < 4096; i += NTHR) {
        int k8 = i >> 5, ln = i & 31;
        int n = ln >> 2, kl = ln & 3;
        size_t rowo = (size_t)(c0 + n) * K1 + k8 * 8 + kl;
        g_w1frag[blockIdx.x * 4096 + i] =
            make_float2(tf32r(W1[rowo]), tf32r(W1[rowo + 4]));
    }
    gbar();

    for (int t = 0; t < 256; ++t) {
        const int p = t & 1;
        const float* detP = g_det[p];
        float*       detN = g_det[p ^ 1];

        // ===== phase 1: emb = relu(stoch @ Ws^T + actemb), fp32, K=32 =====
        {
            float4* stS = R4;           // 64 x 9 f4
            float4* wS1 = R4 + 576;     // 8 x 9 f4
            {
                int row = tid >> 3, k4 = tid & 7;
                stS[row * 9 + k4] = *(const float4*)(g_stoch + row * 32 + k4 * 4);
            }
            if (tid < 64) {
                int c = tid >> 3, k4 = tid & 7;
                wS1[c * 9 + k4] = *(const float4*)(Wsa + (size_t)(c0g + c) * 96 + k4 * 4);
            }
            __syncthreads();
            u64 a = 0;
            #pragma unroll
            for (int k4 = 0; k4 < 8; ++k4) {
                ull2 x = *(const ull2*)(stS + pr * 9 + k4);
                ull2 w = *(const ull2*)(wS1 + pc * 9 + k4);
                a = fma2(w.x, x.x, a); a = fma2(w.y, x.y, a);
            }
            int col = c0g + pc;
            float base = g_actemb[((size_t)pr * 256 + t) * 1024 + col];
            float v = fmaxf(hsum(a) + base, 0.f);
            g_embf[fragIdx(pr, col)] = tf32r(v);
        }
        gbar();

        // ===== phase 2: GRU via tf32 mma — flat, sync-free mainloop =====
        {
            const float* Af = cth ? g_detf[p] : g_embf;
            float acc[3][4];
            #pragma unroll
            for (int g = 0; g < 3; ++g)
                #pragma unroll
                for (int e = 0; e < 4; ++e) acc[g][e] = 0.f;

            const float2* wf = wfS + (cth * 3) * 4096;
            #pragma unroll 4
            for (int q = 0; q < 64; ++q) {
                int k8 = ks * 64 + q;
                float4 av = *(const float4*)(Af + ((size_t)(k8 * 4 + rb) * 32 + lane) * 4);
                #pragma unroll
                for (int g = 0; g < 3; ++g) {
                    float2 bv = wf[g * 4096 + k8 * 32 + lane];
                    mma8(acc[g], av, bv);
                }
            }
            // dump all partial D tiles
            #pragma unroll
            for (int g = 0; g < 3; ++g)
                R4[((((rb * 2 + ks) * 2 + cth) * 3 + g) * 32) + lane] =
                    make_float4(acc[g][0], acc[g][1], acc[g][2], acc[g][3]);
            __syncthreads();

            // gate math: one thread per output element
            {
                int row = tid >> 3, coll = tid & 7, col = c0g + coll;
                int rbw = row >> 4, rp = row & 15;
                int lanew = (rp & 7) * 4 + (coll >> 1);
                int comp  = (coll & 1) + ((rp >> 3) << 1);
                float gi[3], gh[3];
                #pragma unroll
                for (int g = 0; g < 3; ++g) {
                    int b0 = ((((rbw * 2 + 0) * 2 + 0) * 3 + g) * 32 + lanew) * 4 + comp;
                    int b1 = ((((rbw * 2 + 1) * 2 + 0) * 3 + g) * 32 + lanew) * 4 + comp;
                    gi[g] = Rf[b0] + Rf[b1] + bih[col + 1024 * g];
                    int c0i = ((((rbw * 2 + 0) * 2 + 1) * 3 + g) * 32 + lanew) * 4 + comp;
                    int c1i = ((((rbw * 2 + 1) * 2 + 1) * 3 + g) * 32 + lanew) * 4 + comp;
                    gh[g] = Rf[c0i] + Rf[c1i] + bhh[col + 1024 * g];
                }
                float r = sigm(gi[0] + gh[0]);
                float z = sigm(gi[1] + gh[1]);
                float n = tanhf(gi[2] + r * gh[2]);
                float hp = detP[(size_t)row * 1024 + col];
                float hw = (1.f - z) * n + z * hp;
                detN[(size_t)row * 1024 + col] = hw;
                out[((size_t)row * 256 + t) * 1216 + col] = hw;
                g_detf[p ^ 1][fragIdx(row, col)] = tf32r(hw);
            }
        }
        gbar();

        // ===== phase 3: h1/hq first layer via tf32 mma (K=1024, 4-way K-split) =====
        {
            const float* Df = g_detf[p ^ 1];
            const float2* w1f = g_w1frag + blockIdx.x * 4096;
            float acc[4] = {0.f, 0.f, 0.f, 0.f};
            #pragma unroll 4
            for (int q = 0; q < 32; ++q) {
                int k8 = ks3 * 32 + q;
                float4 av = *(const float4*)(Df + ((size_t)(k8 * 4 + rb3) * 32 + lane) * 4);
                float2 bv = w1f[k8 * 32 + lane];
                mma8(acc, av, bv);
            }
            if (ks3 > 0)
                R4[(rb3 * 3 + (ks3 - 1)) * 32 + lane] =
                    make_float4(acc[0], acc[1], acc[2], acc[3]);
            __syncthreads();
            if (ks3 == 0) {
                #pragma unroll
                for (int s = 0; s < 3; ++s) {
                    float4 v = R4[(rb3 * 3 + s) * 32 + lane];
                    acc[0] += v.x; acc[1] += v.y; acc[2] += v.z; acc[3] += v.w;
                }
                float* dst = isQ ? g_hq : g_h1;
                int rbase = rb3 * 16 + (lane >> 2);
                int n0 = (lane & 3) * 2;
                #pragma unroll
                for (int e = 0; e < 4; ++e) {
                    int row = rbase + ((e >> 1) << 3);
                    int col = c0 + n0 + (e & 1);
                    float base = isQ ? g_obsq[((size_t)row * 256 + t) * 512 + col]
                                     : bp1[col];
                    dst[(size_t)row * 512 + col] = fmaxf(acc[e] + base, 0.f);
                }
            }
        }
        gbar();

        // ===== phase 4: heads (fp32) =====
        {
            const int gw = blockIdx.x * 16 + wrp;
            #pragma unroll
            for (int i = 0; i < 2; ++i) {
                int pi    = gw * 2 + i;
                int which = pi & 1;
                int s     = (pi >> 1) & 31;
                int bb    = pi >> 6;
                const float* hv = (which ? g_hq : g_h1) + (size_t)bb * 512;
                const float* W2 = which ? Wq2 : Wp2;
                u64 am = 0, asd = 0;
                #pragma unroll
                for (int q = 0; q < 4; ++q) {
                    float4 xf = __ldcg((const float4*)(hv + lane * 16 + q * 4));
                    ull2 x = *(ull2*)&xf;
                    ull2 u = *(const ull2*)(W2 + (size_t)s * 512 + lane * 16 + q * 4);
                    ull2 v = *(const ull2*)(W2 + (size_t)(s + 32) * 512 + lane * 16 + q * 4);
                    am  = fma2(u.x, x.x, am);  am  = fma2(u.y, x.y, am);
                    asd = fma2(v.x, x.x, asd); asd = fma2(v.y, x.y, asd);
                }
                float sm = hsum(am), ss = hsum(asd);
                #pragma unroll
                for (int o = 16; o; o >>= 1) {
                    sm += __shfl_xor_sync(0xffffffffu, sm, o);
                    ss += __shfl_xor_sync(0xffffffffu, ss, o);
                }
                if (lane == 0) {
                    const float* b2 = which ? bq2 : bp2;
                    float mean = sm + b2[s];
                    float stdv = softplusf(ss + b2[s + 32]) + 1e-5f;
                    const float* nz = which ? nzq : nzp;
                    float e  = nz[((size_t)bb * 256 + t) * 32 + s];
                    float st = mean + stdv * e;
                    size_t base = ((size_t)bb * 256 + t) * 1216 + 1024 + which * 96;
                    out[base + s]      = mean;
                    out[base + 32 + s] = stdv;
                    out[base + 64 + s] = st;
                    if (which) g_stoch[bb * 32 + s] = st;
                }
            }
        }
        gbar();
    }
}

extern "C" void kernel_launch(void* const* d_in, const int* in_sizes, int n_in,
                              void* d_out, int out_size) {
    (void)in_sizes; (void)n_in; (void)out_size;
    cudaFuncSetAttribute((const void*)obsq_kernel,
                         cudaFuncAttributeMaxDynamicSharedMemorySize, 50176);
    cudaFuncSetAttribute((const void*)actemb_kernel,
                         cudaFuncAttributeMaxDynamicSharedMemorySize, 50176);
    cudaFuncSetAttribute((const void*)rssm_kernel,
                         cudaFuncAttributeMaxDynamicSharedMemorySize, SMEM_BYTES);
    actemb_kernel<<<2048, 256, 50176>>>(
        (const float*)d_in[1], (const float*)d_in[4], (const float*)d_in[5]);
    obsq_kernel<<<1024, 256, 50176>>>(
        (const float*)d_in[0], (const float*)d_in[14], (const float*)d_in[15]);
    rssm_kernel<<<NCTA, NTHR, SMEM_BYTES>>>(
        (const float*)d_in[0],  (const float*)d_in[1],
        (const float*)d_in[2],  (const float*)d_in[3],
        (const float*)d_in[4],  (const float*)d_in[5],
        (const float*)d_in[6],  (const float*)d_in[7],
        (const float*)d_in[8],  (const float*)d_in[9],
        (const float*)d_in[10], (const float*)d_in[11],
        (const float*)d_in[12], (const float*)d_in[13],
        (const float*)d_in[14], (const float*)d_in[15],
        (const float*)d_in[16], (const float*)d_in[17],
        (float*)d_out);
}